// round 15
// baseline (speedup 1.0000x reference)
#include <cuda_runtime.h>
#include <math.h>

// Problem constants (KWinners2d: B=64, C=128, H=W=56)
#define NB      64
#define NC      128
#define HW      3136
#define NPB     401408          // per-batch n = C*H*W
#define NPB4    (NPB/4)         // 100352 float4 per batch
#define HW4     784
#define NBINS   8192            // 13-bit coarse histogram
#define CAP     (1<<17)         // candidate buffer per batch
#define CPB_S   8               // CTAs per batch, sample pass
#define CPB_C   32              // CTAs per batch, write pass
#define STAGE   1024            // per-CTA candidate staging entries
#define MS      50176           // sampled values per batch = NPB/8
#define MARGIN  350             // ~5.2 sigma of sampled-rank noise

// -------- global scratch (static __device__, no allocation) --------
// invariant: g_hist / g_done / g_cand_cnt / g_above are zero at kernel_launch
// entry (zero-initialized at load; the sample finalizer re-zeroes them)
__device__ unsigned int       g_hist [NB * NBINS];   // sampled coarse hist
__device__ unsigned int       g_done[NB];
__device__ unsigned int       g_cand_cnt[NB];
__device__ unsigned int       g_bhi[NB];
__device__ unsigned int       g_blo[NB];
__device__ float              g_Thi[NB];             // float thresholds
__device__ float              g_Tlo[NB];
__device__ unsigned int       g_above[NB];
__device__ unsigned long long g_cand[(size_t)NB * CAP];      // (key<<32)|idx
__device__ float              g_cand_val[(size_t)NB * CAP];  // original x value

// order-preserving key for f32: larger float -> larger uint
__device__ __forceinline__ unsigned okey(float f) {
    unsigned u = __float_as_uint(f);
    unsigned s = (unsigned)((int)u >> 31);
    return u ^ (s | 0x80000000u);
}
// inverse: float whose okey equals k
__device__ __forceinline__ float inv_okey(unsigned k) {
    unsigned u = (k & 0x80000000u) ? (k & 0x7FFFFFFFu) : ~k;
    return __uint_as_float(u);
}

__device__ __forceinline__ float boost_factor(int k, float duty) {
    float td = (float)((double)k / (double)NPB);
    float arg = td - duty;
    return (float)exp((double)arg);   // correctly-rounded f32 result
}

// block-wide exclusive prefix sum, blockDim.x == 1024 exactly
__device__ __forceinline__ unsigned excl_scan1024(unsigned v, unsigned* s_w, int tid) {
    __syncthreads();                              // protect s_w reuse
    int lane = tid & 31, wid = tid >> 5;
    unsigned inc = v;
    #pragma unroll
    for (int o = 1; o < 32; o <<= 1) {
        unsigned n = __shfl_up_sync(0xffffffffu, inc, o);
        if (lane >= o) inc += n;
    }
    if (lane == 31) s_w[wid] = inc;
    __syncthreads();
    if (wid == 0) {
        unsigned w = s_w[lane];
        #pragma unroll
        for (int o = 1; o < 32; o <<= 1) {
            unsigned n = __shfl_up_sync(0xffffffffu, w, o);
            if (lane >= o) w += n;
        }
        s_w[lane] = w;
    }
    __syncthreads();
    unsigned base = wid ? s_w[wid - 1] : 0u;
    return base + inc - v;
}

// -------- kernel 1: sampled coarse histogram, 8 CTAs/batch; last CTA of
// each batch computes the window + thresholds and re-zeroes scratch --------
__global__ void __launch_bounds__(256) sample_kernel(
        const float* __restrict__ x,
        const float* __restrict__ duty,
        const int* __restrict__ kp) {
    __shared__ unsigned s_hist[NBINS];
    __shared__ float    s_fac[NC];
    __shared__ unsigned s_last;
    __shared__ unsigned s_wt[8];
    __shared__ unsigned s_res[2];
    int tid = threadIdx.x;
    for (int i = tid; i < NBINS; i += 256) s_hist[i] = 0;
    if (tid < NC) s_fac[tid] = boost_factor(*kp, duty[tid]);
    __syncthreads();

    int batch = blockIdx.x / CPB_S;
    int slice = blockIdx.x % CPB_S;
    const float4* x4 = (const float4*)x + (size_t)batch * NPB4;
    int base = slice * (NPB4 / CPB_S);         // 12544 region per CTA
    // 1568 sampled float4: warp reads 32 contiguous float4 (512B), skips 8x
    for (int j = tid; j < 1568; j += 256) {
        int q = base + ((j >> 5) << 8) + (j & 31);
        float f = s_fac[q / HW4];
        float4 v = x4[q];
        unsigned b0 = okey(v.x * f) >> 19;
        unsigned b1 = okey(v.y * f) >> 19;
        unsigned b2 = okey(v.z * f) >> 19;
        unsigned b3 = okey(v.w * f) >> 19;
        unsigned c0 = 1, c1 = 1, c2 = 1, c3 = 1;
        if (b1 == b0) { c0++; c1 = 0; }
        if (b2 == b0) { c0++; c2 = 0; }
        else if (c1 && b2 == b1) { c1++; c2 = 0; }
        if (b3 == b0) { c0++; c3 = 0; }
        else if (c1 && b3 == b1) { c1++; c3 = 0; }
        else if (c2 && b3 == b2) { c2++; c3 = 0; }
        atomicAdd(&s_hist[b0], c0);
        if (c1) atomicAdd(&s_hist[b1], c1);
        if (c2) atomicAdd(&s_hist[b2], c2);
        if (c3) atomicAdd(&s_hist[b3], c3);
    }
    __syncthreads();
    unsigned* gh = &g_hist[batch * NBINS];
    for (int i = tid; i < NBINS; i += 256)
        if (s_hist[i]) atomicAdd(&gh[i], s_hist[i]);

    // ---- election: last CTA of this batch finalizes the window ----
    __threadfence();
    if (tid == 0) s_last = atomicAdd(&g_done[batch], 1u);
    __syncthreads();
    if (s_last != CPB_S - 1) return;
    __threadfence();                            // acquire others' merges

    // suffix-position scan at 256 threads, 32 descending bins per thread
    unsigned csum = 0;
    int top = NBINS - 1 - tid * 32;
    #pragma unroll 8
    for (int i = 0; i < 32; i++) csum += gh[top - i];
    int lane = tid & 31, wrp = tid >> 5;
    unsigned inc = csum;
    #pragma unroll
    for (int o = 1; o < 32; o <<= 1) {
        unsigned n = __shfl_up_sync(0xffffffffu, inc, o);
        if (lane >= o) inc += n;
    }
    if (lane == 31) s_wt[wrp] = inc;
    __syncthreads();
    if (tid < 8) {
        unsigned w = s_wt[tid];
        #pragma unroll
        for (int o = 1; o < 8; o <<= 1) {
            unsigned n = __shfl_up_sync(0xFFu, w, o);
            if (tid >= o) w += n;
        }
        s_wt[tid] = w;
    }
    __syncthreads();
    unsigned excl = (wrp ? s_wt[wrp - 1] : 0u) + inc - csum;

    unsigned k  = (unsigned)(*kp);
    unsigned ks = (unsigned)((unsigned long long)k * MS / NPB);
    unsigned khi = (ks > MARGIN) ? ks - MARGIN : 1u;
    unsigned klo = ks + MARGIN; if (klo > MS) klo = MS;

    if (excl < khi && khi <= excl + csum) {
        unsigned c = excl;
        for (int i = 0; i < 32; i++) {
            unsigned hv = gh[top - i];
            if (c + hv >= khi) { s_res[0] = (unsigned)(top - i); break; }
            c += hv;
        }
    }
    if (excl < klo && klo <= excl + csum) {
        unsigned c = excl;
        for (int i = 0; i < 32; i++) {
            unsigned hv = gh[top - i];
            if (c + hv >= klo) { s_res[1] = (unsigned)(top - i); break; }
            c += hv;
        }
    }
    __syncthreads();
    // re-zero this batch's histogram for the next graph replay
    for (int i = 0; i < 32; i++) gh[top - i] = 0;
    if (tid == 0) {
        unsigned bhi = s_res[0], blo = s_res[1];
        if (bhi > 8190u) bhi = 8190u;          // keep (bhi+1)<<19 in 32 bits
        if (blo > bhi) blo = bhi;
        if (bhi == 4095u) bhi = 4096u;         // avoid T_hi == +/-0.0
        if (blo == 4096u) blo = 4095u;         // avoid T_lo == +/-0.0
        g_bhi[batch] = bhi;
        g_blo[batch] = blo;
        g_Thi[batch] = inv_okey((bhi + 1u) << 19);
        g_Tlo[batch] = inv_okey(blo << 19);
        g_cand_cnt[batch] = 0;                 // zero counters for write pass
        g_above[batch] = 0;
        g_done[batch] = 0;                     // reset election for next replay
    }
}

// -------- kernel 2: write output, exact above-count, stage window cands ----
__global__ void __launch_bounds__(256, 8) write_kernel(
        const float* __restrict__ x,
        const float* __restrict__ duty,
        const int* __restrict__ kp,
        float* __restrict__ out) {
    __shared__ float              s_fac[4];
    __shared__ unsigned long long s_buf[STAGE];
    __shared__ float              s_val[STAGE];
    __shared__ unsigned           s_cnt, s_w, s_base;
    int tid = threadIdx.x;
    int batch = blockIdx.x / CPB_C;
    int slice = blockIdx.x % CPB_C;
    if (tid < NC / CPB_C)                       // only this CTA's 4 channels
        s_fac[tid] = boost_factor(*kp, duty[slice * (NC / CPB_C) + tid]);
    if (tid == 0) { s_cnt = 0; s_w = 0; }
    __syncthreads();

    float Thi = g_Thi[batch];
    float Tlo = g_Tlo[batch];
    const float4* x4 = (const float4*)x + (size_t)batch * NPB4;
    float4*       o4 = (float4*)out     + (size_t)batch * NPB4;
    const int PER = NPB4 / CPB_C;              // 3136 = 4 channels
    int qb = slice * PER;
    unsigned wc = 0;

    #pragma unroll 2
    for (int i = tid; i < PER; i += 256) {
        int q = qb + i;
        float f = s_fac[i / HW4];              // channel within CTA: 0..3
        float4 v = x4[q];
        float vf0 = v.x * f, vf1 = v.y * f, vf2 = v.z * f, vf3 = v.w * f;
        bool w0 = vf0 >= Thi, w1 = vf1 >= Thi, w2 = vf2 >= Thi, w3 = vf3 >= Thi;
        float4 o;
        o.x = w0 ? v.x : 0.0f;
        o.y = w1 ? v.y : 0.0f;
        o.z = w2 ? v.z : 0.0f;
        o.w = w3 ? v.w : 0.0f;
        o4[q] = o;
        wc += (unsigned)w0 + (unsigned)w1 + (unsigned)w2 + (unsigned)w3;
        bool c0 = (vf0 >= Tlo) & !w0;
        bool c1 = (vf1 >= Tlo) & !w1;
        bool c2 = (vf2 >= Tlo) & !w2;
        bool c3 = (vf3 >= Tlo) & !w3;
        if (c0 | c1 | c2 | c3) {                // ~1.5% of iterations
            unsigned e = (unsigned)q * 4u;
            if (c0) {
                unsigned p = atomicAdd(&s_cnt, 1u);
                unsigned long long cv = ((unsigned long long)okey(vf0) << 32) | (e + 0u);
                if (p < STAGE) { s_buf[p] = cv; s_val[p] = v.x; }
                else { unsigned g = atomicAdd(&g_cand_cnt[batch], 1u);
                       if (g < CAP) { g_cand[(size_t)batch * CAP + g] = cv;
                                      g_cand_val[(size_t)batch * CAP + g] = v.x; } }
            }
            if (c1) {
                unsigned p = atomicAdd(&s_cnt, 1u);
                unsigned long long cv = ((unsigned long long)okey(vf1) << 32) | (e + 1u);
                if (p < STAGE) { s_buf[p] = cv; s_val[p] = v.y; }
                else { unsigned g = atomicAdd(&g_cand_cnt[batch], 1u);
                       if (g < CAP) { g_cand[(size_t)batch * CAP + g] = cv;
                                      g_cand_val[(size_t)batch * CAP + g] = v.y; } }
            }
            if (c2) {
                unsigned p = atomicAdd(&s_cnt, 1u);
                unsigned long long cv = ((unsigned long long)okey(vf2) << 32) | (e + 2u);
                if (p < STAGE) { s_buf[p] = cv; s_val[p] = v.z; }
                else { unsigned g = atomicAdd(&g_cand_cnt[batch], 1u);
                       if (g < CAP) { g_cand[(size_t)batch * CAP + g] = cv;
                                      g_cand_val[(size_t)batch * CAP + g] = v.z; } }
            }
            if (c3) {
                unsigned p = atomicAdd(&s_cnt, 1u);
                unsigned long long cv = ((unsigned long long)okey(vf3) << 32) | (e + 3u);
                if (p < STAGE) { s_buf[p] = cv; s_val[p] = v.w; }
                else { unsigned g = atomicAdd(&g_cand_cnt[batch], 1u);
                       if (g < CAP) { g_cand[(size_t)batch * CAP + g] = cv;
                                      g_cand_val[(size_t)batch * CAP + g] = v.w; } }
            }
        }
    }
    // exact winners-above-window count: one global atomic per CTA
    #pragma unroll
    for (int o = 16; o; o >>= 1) wc += __shfl_down_sync(0xffffffffu, wc, o);
    if ((tid & 31) == 0 && wc) atomicAdd(&s_w, wc);
    __syncthreads();
    if (tid == 0) {
        if (s_w) atomicAdd(&g_above[batch], s_w);
        s_base = atomicAdd(&g_cand_cnt[batch], min(s_cnt, (unsigned)STAGE));
    }
    __syncthreads();
    unsigned cnt = min(s_cnt, (unsigned)STAGE);
    unsigned cb = s_base;
    for (unsigned j = tid; j < cnt; j += 256) {
        unsigned pos = cb + j;
        if (pos < CAP) {
            g_cand[(size_t)batch * CAP + pos] = s_buf[j];
            g_cand_val[(size_t)batch * CAP + pos] = s_val[j];
        }
    }
}

// -------- kernel 3: exact selection (parallel scans) or exact fallback -----
__global__ void __launch_bounds__(1024) final_kernel(
        const float* __restrict__ x,
        const float* __restrict__ duty,
        const int* __restrict__ kp,
        float* __restrict__ out) {
    __shared__ unsigned s_w[32];
    __shared__ float    s_fac[NC];
    __shared__ unsigned s_big[NBINS];     // hist, then stash[0..4095] + L2 hist[4096..5119]
    __shared__ unsigned s_sc[8];
    int batch = blockIdx.x, tid = threadIdx.x;
    unsigned k = (unsigned)(*kp);
    unsigned m = g_cand_cnt[batch];
    unsigned above = g_above[batch];
    unsigned blo = g_blo[batch], bhi = g_bhi[batch];
    unsigned long long* cand = &g_cand[(size_t)batch * CAP];
    const float*        cval = &g_cand_val[(size_t)batch * CAP];
    const float* xb = x   + (size_t)batch * NPB;
    float*       ob = out + (size_t)batch * NPB;

    bool valid = (above < k) && (k <= above + m) && (m <= (unsigned)CAP) &&
                 (bhi - blo < 16u);
    unsigned r = 0, B1 = 0, g1 = 0, eq = 0;
    unsigned base19 = blo << 19;

    if (valid) {
        r = k - above;
        if (r >= m) {                       // everything in the window wins
            for (unsigned j = tid; j < m; j += 1024) {
                unsigned idx = (unsigned)cand[j];
                ob[idx] = cval[j];
            }
            return;
        }
        // build rel-key level-1 histogram (rel>>10, 8192 bins) over candidates
        for (int i = tid; i < NBINS; i += 1024) s_big[i] = 0;
        __syncthreads();
        for (unsigned j = tid; j < m; j += 1024) {
            unsigned rel = (unsigned)(cand[j] >> 32) - base19;   // < 2^23
            atomicAdd(&s_big[rel >> 10], 1u);
        }
        __syncthreads();
        // parallel suffix scan for rank r
        unsigned h[8], sum = 0;
        int top = NBINS - 1 - tid * 8;
        #pragma unroll
        for (int i = 0; i < 8; i++) { h[i] = s_big[top - i]; sum += h[i]; }
        unsigned excl = excl_scan1024(sum, s_w, tid);
        if (excl < r && r <= excl + sum) {
            unsigned c = excl;
            #pragma unroll
            for (int i = 0; i < 8; i++) {
                if (c + h[i] >= r) { s_sc[0] = (unsigned)(top - i); s_sc[1] = c; break; }
                c += h[i];
            }
        }
        __syncthreads();
        B1 = s_sc[0]; g1 = s_sc[1];
        eq = s_big[B1];
        if (eq > 4096u) valid = false;      // stash overflow -> fallback
        __syncthreads();
    }

    if (valid) {
        // ---------------- fast exact path ----------------
        unsigned r1 = r - g1;               // needed among the B1 group
        unsigned* s_stash = s_big;          // 4096 packed (rel10<<19)|idx
        unsigned* s_h2    = s_big + 4096;   // 1024-bin L2 hist
        for (int i = tid; i < 1024; i += 1024) s_h2[i] = 0;
        if (tid == 0) s_sc[2] = 0;
        __syncthreads();
        for (unsigned j = tid; j < m; j += 1024) {
            unsigned long long cv = cand[j];
            unsigned rel = (unsigned)(cv >> 32) - base19;
            unsigned hi = rel >> 10;
            unsigned idx = (unsigned)cv;
            if (hi > B1) ob[idx] = cval[j];          // certain winner, no x read
            else if (hi == B1) {
                unsigned p = atomicAdd(&s_sc[2], 1u);
                if (p < 4096u) {
                    s_stash[p] = ((rel & 1023u) << 19) | idx;
                    atomicAdd(&s_h2[rel & 1023u], 1u);
                }
            }
        }
        __syncthreads();
        unsigned e = min(s_sc[2], 4096u);   // == eq <= 4096
        // level-2: parallel suffix scan, one bin per thread
        {
            int b = 1023 - tid;
            unsigned val = (tid < 1024) ? s_h2[b] : 0;
            unsigned excl = excl_scan1024(val, s_w, tid);
            if (excl < r1 && r1 <= excl + val) { s_sc[3] = (unsigned)b; s_sc[4] = r1 - excl; }
        }
        __syncthreads();
        unsigned tl2 = s_sc[3], r2 = s_sc[4];
        // winners among stash; ties at exact threshold by LOWEST index
        for (unsigned j = tid; j < e; j += 1024) {
            unsigned v = s_stash[j];
            unsigned r10 = v >> 19, idx = v & 0x7FFFFu;
            if (r10 > tl2) ob[idx] = xb[idx];
            else if (r10 == tl2) {
                unsigned rank = 0;
                for (unsigned l = 0; l < e; l++) {
                    unsigned w2 = s_stash[l];
                    rank += ((w2 >> 19) == tl2 && (w2 & 0x7FFFFu) < idx) ? 1u : 0u;
                }
                if (rank < r2) ob[idx] = xb[idx];
            }
        }
        return;
    }

    // ---------------- exact fallback: full recompute for this batch --------
    if (tid < NC) s_fac[tid] = boost_factor((int)k, duty[tid]);
    for (int i = tid; i < NBINS; i += 1024) s_big[i] = 0;
    __syncthreads();
    const float4* x4 = (const float4*)xb;
    for (int q = tid; q < NPB4; q += 1024) {
        float f = s_fac[q / HW4];
        float4 v = x4[q];
        atomicAdd(&s_big[okey(v.x * f) >> 19], 1u);
        atomicAdd(&s_big[okey(v.y * f) >> 19], 1u);
        atomicAdd(&s_big[okey(v.z * f) >> 19], 1u);
        atomicAdd(&s_big[okey(v.w * f) >> 19], 1u);
    }
    __syncthreads();
    {   // parallel scan for exact bstar
        unsigned h[8], sum = 0;
        int top = NBINS - 1 - tid * 8;
        #pragma unroll
        for (int i = 0; i < 8; i++) { h[i] = s_big[top - i]; sum += h[i]; }
        unsigned excl = excl_scan1024(sum, s_w, tid);
        if (excl < k && k <= excl + sum) {
            unsigned c = excl;
            #pragma unroll
            for (int i = 0; i < 8; i++) {
                if (c + h[i] >= k) { s_sc[0] = (unsigned)(top - i); s_sc[1] = c; break; }
                c += h[i];
            }
        }
    }
    __syncthreads();
    unsigned bstar = s_sc[0];
    unsigned rr = k - s_sc[1];
    if (tid == 0) s_sc[2] = 0;
    __syncthreads();
    float4* o4 = (float4*)ob;
    for (int q = tid; q < NPB4; q += 1024) {
        float f = s_fac[q / HW4];
        float4 v = x4[q];
        unsigned k0 = okey(v.x * f), k1 = okey(v.y * f);
        unsigned k2 = okey(v.z * f), k3 = okey(v.w * f);
        unsigned b0 = k0 >> 19, b1 = k1 >> 19, b2 = k2 >> 19, b3 = k3 >> 19;
        float4 o;
        o.x = (b0 > bstar) ? v.x : 0.0f;
        o.y = (b1 > bstar) ? v.y : 0.0f;
        o.z = (b2 > bstar) ? v.z : 0.0f;
        o.w = (b3 > bstar) ? v.w : 0.0f;
        o4[q] = o;
        unsigned e = (unsigned)q * 4u;
        if (b0 == bstar) { unsigned p = atomicAdd(&s_sc[2], 1u);
            if (p < CAP) cand[p] = ((unsigned long long)k0 << 32) | (e + 0u); }
        if (b1 == bstar) { unsigned p = atomicAdd(&s_sc[2], 1u);
            if (p < CAP) cand[p] = ((unsigned long long)k1 << 32) | (e + 1u); }
        if (b2 == bstar) { unsigned p = atomicAdd(&s_sc[2], 1u);
            if (p < CAP) cand[p] = ((unsigned long long)k2 << 32) | (e + 2u); }
        if (b3 == bstar) { unsigned p = atomicAdd(&s_sc[2], 1u);
            if (p < CAP) cand[p] = ((unsigned long long)k3 << 32) | (e + 3u); }
    }
    __syncthreads();
    unsigned m2 = min(s_sc[2], (unsigned)CAP);
    if (rr >= m2) {
        for (unsigned j = tid; j < m2; j += 1024) {
            unsigned idx = (unsigned)cand[j];
            ob[idx] = xb[idx];
        }
        return;
    }
    unsigned fb19 = bstar << 19;
    // L1: 512 bins on rel>>10
    for (int i = tid; i < 512; i += 1024) s_big[i] = 0;
    __syncthreads();
    for (unsigned j = tid; j < m2; j += 1024) {
        unsigned rel = (unsigned)(cand[j] >> 32) - fb19;
        atomicAdd(&s_big[rel >> 10], 1u);
    }
    __syncthreads();
    if (tid == 0) {
        unsigned cum = 0;
        for (int b = 511;; b--) {
            unsigned h = s_big[b];
            if (cum + h >= rr) { s_sc[3] = (unsigned)b; s_sc[4] = cum; break; }
            cum += h;
        }
    }
    __syncthreads();
    unsigned tl1 = s_sc[3];
    unsigned r1 = rr - s_sc[4];
    unsigned* s_l2 = s_big + 1024;
    for (int i = tid; i < 1024; i += 1024) s_l2[i] = 0;
    __syncthreads();
    for (unsigned j = tid; j < m2; j += 1024) {
        unsigned rel = (unsigned)(cand[j] >> 32) - fb19;
        if ((rel >> 10) == tl1) atomicAdd(&s_l2[rel & 1023u], 1u);
    }
    __syncthreads();
    if (tid == 0) {
        unsigned cum = 0;
        for (int b = 1023;; b--) {
            unsigned h = s_l2[b];
            if (cum + h >= r1) { s_sc[5] = (unsigned)b; s_sc[6] = r1 - cum; break; }
            cum += h;
        }
    }
    __syncthreads();
    unsigned tl = (tl1 << 10) | s_sc[5];
    unsigned r2 = s_sc[6];
    for (unsigned j = tid; j < m2; j += 1024) {
        unsigned long long cv = cand[j];
        unsigned rel = (unsigned)(cv >> 32) - fb19;
        unsigned idx = (unsigned)cv;
        if (rel > tl) ob[idx] = xb[idx];
        else if (rel == tl) {
            unsigned rank = 0;
            for (unsigned l = 0; l < m2; l++) {
                unsigned long long cw = cand[l];
                rank += (((unsigned)(cw >> 32) - fb19) == tl &&
                         (unsigned)cw < idx) ? 1u : 0u;
            }
            if (rank < r2) ob[idx] = xb[idx];
        }
    }
}

extern "C" void kernel_launch(void* const* d_in, const int* in_sizes, int n_in,
                              void* d_out, int out_size) {
    const float* x    = (const float*)d_in[0];
    const float* duty = (const float*)d_in[1];
    const int*   kp   = (const int*)d_in[2];
    float*       out  = (float*)d_out;

    sample_kernel<<<NB * CPB_S, 256>>>(x, duty, kp);
    write_kernel<<<NB * CPB_C, 256>>>(x, duty, kp, out);
    final_kernel<<<NB, 1024>>>(x, duty, kp, out);
}

// round 16
// speedup vs baseline: 1.4424x; 1.4424x over previous
#include <cuda_runtime.h>
#include <math.h>

// Problem constants (KWinners2d: B=64, C=128, H=W=56)
#define NB      64
#define NC      128
#define HW      3136
#define NPB     401408          // per-batch n = C*H*W
#define NPB4    (NPB/4)         // 100352 float4 per batch
#define HW4     784
#define NBINS   8192            // 13-bit coarse histogram
#define CAP     (1<<17)         // candidate buffer per batch
#define CPB_S   8               // CTAs per batch, sample pass
#define CPB_C   32              // CTAs per batch, write pass
#define SCC     8               // CTAs per batch, scatter pass
#define STAGE   1024            // per-CTA candidate staging entries
#define MS      50176           // sampled values per batch = NPB/8
#define MARGIN  350             // ~5.2 sigma of sampled-rank noise

// -------- global scratch (static __device__, no allocation) --------
__device__ unsigned int       g_hist [NB * NBINS];   // sampled coarse hist
__device__ unsigned int       g_cand_cnt[NB];
__device__ unsigned int       g_bhi[NB];
__device__ unsigned int       g_blo[NB];
__device__ float              g_Thi[NB];             // float thresholds
__device__ float              g_Tlo[NB];
__device__ unsigned int       g_above[NB];
__device__ long long          g_tl[NB];              // rel threshold for scatter
__device__ unsigned long long g_cand[(size_t)NB * CAP];      // (key<<32)|idx
__device__ float              g_cand_val[(size_t)NB * CAP];  // original x value

// order-preserving key for f32: larger float -> larger uint
__device__ __forceinline__ unsigned okey(float f) {
    unsigned u = __float_as_uint(f);
    unsigned s = (unsigned)((int)u >> 31);
    return u ^ (s | 0x80000000u);
}
// inverse: float whose okey equals k
__device__ __forceinline__ float inv_okey(unsigned k) {
    unsigned u = (k & 0x80000000u) ? (k & 0x7FFFFFFFu) : ~k;
    return __uint_as_float(u);
}

__device__ __forceinline__ float boost_factor(int k, float duty) {
    float td = (float)((double)k / (double)NPB);
    float arg = td - duty;
    return (float)exp((double)arg);   // correctly-rounded f32 result
}

// block-wide exclusive prefix sum, blockDim.x == 1024 exactly
__device__ __forceinline__ unsigned excl_scan1024(unsigned v, unsigned* s_w, int tid) {
    __syncthreads();                              // protect s_w reuse
    int lane = tid & 31, wid = tid >> 5;
    unsigned inc = v;
    #pragma unroll
    for (int o = 1; o < 32; o <<= 1) {
        unsigned n = __shfl_up_sync(0xffffffffu, inc, o);
        if (lane >= o) inc += n;
    }
    if (lane == 31) s_w[wid] = inc;
    __syncthreads();
    if (wid == 0) {
        unsigned w = s_w[lane];
        #pragma unroll
        for (int o = 1; o < 32; o <<= 1) {
            unsigned n = __shfl_up_sync(0xffffffffu, w, o);
            if (lane >= o) w += n;
        }
        s_w[lane] = w;
    }
    __syncthreads();
    unsigned base = wid ? s_w[wid - 1] : 0u;
    return base + inc - v;
}

// -------- kernel 0: zero scratch (re-zeroed every graph replay) --------
__global__ void zero_kernel() {
    int total = NB * NBINS;
    int tid = blockIdx.x * blockDim.x + threadIdx.x;
    for (int i = tid; i < total; i += gridDim.x * blockDim.x) g_hist[i] = 0;
    if (blockIdx.x == 0 && threadIdx.x < NB) {
        g_cand_cnt[threadIdx.x] = 0;
        g_above[threadIdx.x] = 0;
    }
}

// -------- kernel 1: sampled coarse histogram, 8 CTAs/batch --------
__global__ void __launch_bounds__(256) sample_kernel(
        const float* __restrict__ x,
        const float* __restrict__ duty,
        const int* __restrict__ kp) {
    __shared__ unsigned s_hist[NBINS];
    __shared__ float    s_fac[NC];
    int tid = threadIdx.x;
    for (int i = tid; i < NBINS; i += 256) s_hist[i] = 0;
    if (tid < NC) s_fac[tid] = boost_factor(*kp, duty[tid]);
    __syncthreads();

    int batch = blockIdx.x / CPB_S;
    int slice = blockIdx.x % CPB_S;
    const float4* x4 = (const float4*)x + (size_t)batch * NPB4;
    int base = slice * (NPB4 / CPB_S);         // 12544 region per CTA
    // 1568 sampled float4: warp reads 32 contiguous float4 (512B), skips 8x
    for (int j = tid; j < 1568; j += 256) {
        int q = base + ((j >> 5) << 8) + (j & 31);
        float f = s_fac[q / HW4];
        float4 v = x4[q];
        unsigned b0 = okey(v.x * f) >> 19;
        unsigned b1 = okey(v.y * f) >> 19;
        unsigned b2 = okey(v.z * f) >> 19;
        unsigned b3 = okey(v.w * f) >> 19;
        unsigned c0 = 1, c1 = 1, c2 = 1, c3 = 1;
        if (b1 == b0) { c0++; c1 = 0; }
        if (b2 == b0) { c0++; c2 = 0; }
        else if (c1 && b2 == b1) { c1++; c2 = 0; }
        if (b3 == b0) { c0++; c3 = 0; }
        else if (c1 && b3 == b1) { c1++; c3 = 0; }
        else if (c2 && b3 == b2) { c2++; c3 = 0; }
        atomicAdd(&s_hist[b0], c0);
        if (c1) atomicAdd(&s_hist[b1], c1);
        if (c2) atomicAdd(&s_hist[b2], c2);
        if (c3) atomicAdd(&s_hist[b3], c3);
    }
    __syncthreads();
    unsigned* gh = &g_hist[batch * NBINS];
    for (int i = tid; i < NBINS; i += 256)
        if (s_hist[i]) atomicAdd(&gh[i], s_hist[i]);
}

// -------- kernel 2: pick window [b_lo, b_hi] + float thresholds ------------
__global__ void __launch_bounds__(1024) window_kernel(const int* __restrict__ kp) {
    __shared__ unsigned s_w[32];
    __shared__ unsigned s_res[2];
    int batch = blockIdx.x, tid = threadIdx.x;
    const unsigned* gh = &g_hist[batch * NBINS];
    unsigned h[8], sum = 0;
    int top = NBINS - 1 - tid * 8;
    #pragma unroll
    for (int i = 0; i < 8; i++) { h[i] = gh[top - i]; sum += h[i]; }
    unsigned excl = excl_scan1024(sum, s_w, tid);   // counts in bins above chunk

    unsigned k  = (unsigned)(*kp);
    unsigned ks = (unsigned)((unsigned long long)k * MS / NPB);
    unsigned khi = (ks > MARGIN) ? ks - MARGIN : 1u;
    unsigned klo = ks + MARGIN; if (klo > MS) klo = MS;

    if (excl < khi && khi <= excl + sum) {
        unsigned c = excl;
        #pragma unroll
        for (int i = 0; i < 8; i++) { if (c + h[i] >= khi) { s_res[0] = (unsigned)(top - i); break; } c += h[i]; }
    }
    if (excl < klo && klo <= excl + sum) {
        unsigned c = excl;
        #pragma unroll
        for (int i = 0; i < 8; i++) { if (c + h[i] >= klo) { s_res[1] = (unsigned)(top - i); break; } c += h[i]; }
    }
    __syncthreads();
    if (tid == 0) {
        unsigned bhi = s_res[0], blo = s_res[1];
        if (bhi > 8190u) bhi = 8190u;          // keep (bhi+1)<<19 in 32 bits
        if (blo > bhi) blo = bhi;
        if (bhi == 4095u) bhi = 4096u;         // avoid T_hi == +/-0.0
        if (blo == 4096u) blo = 4095u;         // avoid T_lo == +/-0.0
        g_bhi[batch] = bhi;
        g_blo[batch] = blo;
        g_Thi[batch] = inv_okey((bhi + 1u) << 19);
        g_Tlo[batch] = inv_okey(blo << 19);
    }
}

// -------- kernel 3: write output, exact above-count, stage window cands ----
__global__ void __launch_bounds__(256, 8) write_kernel(
        const float* __restrict__ x,
        const float* __restrict__ duty,
        const int* __restrict__ kp,
        float* __restrict__ out) {
    __shared__ float              s_fac[4];
    __shared__ unsigned long long s_buf[STAGE];
    __shared__ float              s_val[STAGE];
    __shared__ unsigned           s_cnt, s_w, s_base;
    int tid = threadIdx.x;
    int batch = blockIdx.x / CPB_C;
    int slice = blockIdx.x % CPB_C;
    if (tid < NC / CPB_C)                       // only this CTA's 4 channels
        s_fac[tid] = boost_factor(*kp, duty[slice * (NC / CPB_C) + tid]);
    if (tid == 0) { s_cnt = 0; s_w = 0; }
    __syncthreads();

    float Thi = g_Thi[batch];
    float Tlo = g_Tlo[batch];
    const float4* x4 = (const float4*)x + (size_t)batch * NPB4;
    float4*       o4 = (float4*)out     + (size_t)batch * NPB4;
    const int PER = NPB4 / CPB_C;              // 3136 = 4 channels
    int qb = slice * PER;
    unsigned wc = 0;

    #pragma unroll 2
    for (int i = tid; i < PER; i += 256) {
        int q = qb + i;
        float f = s_fac[i / HW4];              // channel within CTA: 0..3
        float4 v = x4[q];
        float vf0 = v.x * f, vf1 = v.y * f, vf2 = v.z * f, vf3 = v.w * f;
        bool w0 = vf0 >= Thi, w1 = vf1 >= Thi, w2 = vf2 >= Thi, w3 = vf3 >= Thi;
        float4 o;
        o.x = w0 ? v.x : 0.0f;
        o.y = w1 ? v.y : 0.0f;
        o.z = w2 ? v.z : 0.0f;
        o.w = w3 ? v.w : 0.0f;
        o4[q] = o;
        wc += (unsigned)w0 + (unsigned)w1 + (unsigned)w2 + (unsigned)w3;
        bool c0 = (vf0 >= Tlo) & !w0;
        bool c1 = (vf1 >= Tlo) & !w1;
        bool c2 = (vf2 >= Tlo) & !w2;
        bool c3 = (vf3 >= Tlo) & !w3;
        if (c0 | c1 | c2 | c3) {                // ~1.5% of iterations
            unsigned e = (unsigned)q * 4u;
            if (c0) {
                unsigned p = atomicAdd(&s_cnt, 1u);
                unsigned long long cv = ((unsigned long long)okey(vf0) << 32) | (e + 0u);
                if (p < STAGE) { s_buf[p] = cv; s_val[p] = v.x; }
                else { unsigned g = atomicAdd(&g_cand_cnt[batch], 1u);
                       if (g < CAP) { g_cand[(size_t)batch * CAP + g] = cv;
                                      g_cand_val[(size_t)batch * CAP + g] = v.x; } }
            }
            if (c1) {
                unsigned p = atomicAdd(&s_cnt, 1u);
                unsigned long long cv = ((unsigned long long)okey(vf1) << 32) | (e + 1u);
                if (p < STAGE) { s_buf[p] = cv; s_val[p] = v.y; }
                else { unsigned g = atomicAdd(&g_cand_cnt[batch], 1u);
                       if (g < CAP) { g_cand[(size_t)batch * CAP + g] = cv;
                                      g_cand_val[(size_t)batch * CAP + g] = v.y; } }
            }
            if (c2) {
                unsigned p = atomicAdd(&s_cnt, 1u);
                unsigned long long cv = ((unsigned long long)okey(vf2) << 32) | (e + 2u);
                if (p < STAGE) { s_buf[p] = cv; s_val[p] = v.z; }
                else { unsigned g = atomicAdd(&g_cand_cnt[batch], 1u);
                       if (g < CAP) { g_cand[(size_t)batch * CAP + g] = cv;
                                      g_cand_val[(size_t)batch * CAP + g] = v.z; } }
            }
            if (c3) {
                unsigned p = atomicAdd(&s_cnt, 1u);
                unsigned long long cv = ((unsigned long long)okey(vf3) << 32) | (e + 3u);
                if (p < STAGE) { s_buf[p] = cv; s_val[p] = v.w; }
                else { unsigned g = atomicAdd(&g_cand_cnt[batch], 1u);
                       if (g < CAP) { g_cand[(size_t)batch * CAP + g] = cv;
                                      g_cand_val[(size_t)batch * CAP + g] = v.w; } }
            }
        }
    }
    // exact winners-above-window count: one global atomic per CTA
    #pragma unroll
    for (int o = 16; o; o >>= 1) wc += __shfl_down_sync(0xffffffffu, wc, o);
    if ((tid & 31) == 0 && wc) atomicAdd(&s_w, wc);
    __syncthreads();
    if (tid == 0) {
        if (s_w) atomicAdd(&g_above[batch], s_w);
        s_base = atomicAdd(&g_cand_cnt[batch], min(s_cnt, (unsigned)STAGE));
    }
    __syncthreads();
    unsigned cnt = min(s_cnt, (unsigned)STAGE);
    unsigned cb = s_base;
    for (unsigned j = tid; j < cnt; j += 256) {
        unsigned pos = cb + j;
        if (pos < CAP) {
            g_cand[(size_t)batch * CAP + pos] = s_buf[j];
            g_cand_val[(size_t)batch * CAP + pos] = s_val[j];
        }
    }
}

// -------- kernel 4a: exact threshold + tie resolution (or full fallback) ---
__global__ void __launch_bounds__(1024) select_kernel(
        const float* __restrict__ x,
        const float* __restrict__ duty,
        const int* __restrict__ kp,
        float* __restrict__ out) {
    __shared__ unsigned s_w[32];
    __shared__ float    s_fac[NC];
    __shared__ unsigned s_big[NBINS];     // hist, then stash[0..4095] + L2 hist[4096..5119]
    __shared__ unsigned s_sc[8];
    int batch = blockIdx.x, tid = threadIdx.x;
    unsigned k = (unsigned)(*kp);
    unsigned m = g_cand_cnt[batch];
    unsigned above = g_above[batch];
    unsigned blo = g_blo[batch], bhi = g_bhi[batch];
    unsigned long long* cand = &g_cand[(size_t)batch * CAP];
    const float* xb = x   + (size_t)batch * NPB;
    float*       ob = out + (size_t)batch * NPB;

    bool valid = (above < k) && (k <= above + m) && (m <= (unsigned)CAP) &&
                 (bhi - blo < 16u);
    unsigned r = 0, B1 = 0, g1 = 0, eq = 0;
    unsigned base19 = blo << 19;

    if (valid) {
        r = k - above;
        if (r >= m) {                       // everything in the window wins
            if (tid == 0) g_tl[batch] = -1LL;   // scatter writes all
            return;
        }
        // build rel-key level-1 histogram (rel>>10, 8192 bins) over candidates
        for (int i = tid; i < NBINS; i += 1024) s_big[i] = 0;
        __syncthreads();
        for (unsigned j = tid; j < m; j += 1024) {
            unsigned rel = (unsigned)(cand[j] >> 32) - base19;   // < 2^23
            atomicAdd(&s_big[rel >> 10], 1u);
        }
        __syncthreads();
        // parallel suffix scan for rank r
        unsigned h[8], sum = 0;
        int top = NBINS - 1 - tid * 8;
        #pragma unroll
        for (int i = 0; i < 8; i++) { h[i] = s_big[top - i]; sum += h[i]; }
        unsigned excl = excl_scan1024(sum, s_w, tid);
        if (excl < r && r <= excl + sum) {
            unsigned c = excl;
            #pragma unroll
            for (int i = 0; i < 8; i++) {
                if (c + h[i] >= r) { s_sc[0] = (unsigned)(top - i); s_sc[1] = c; break; }
                c += h[i];
            }
        }
        __syncthreads();
        B1 = s_sc[0]; g1 = s_sc[1];
        eq = s_big[B1];
        if (eq > 4096u) valid = false;      // stash overflow -> fallback
        __syncthreads();
    }

    if (valid) {
        // ---------------- fast exact path: threshold + ties only ----------
        unsigned r1 = r - g1;               // needed among the B1 group
        unsigned* s_stash = s_big;          // 4096 packed (rel10<<19)|idx
        unsigned* s_h2    = s_big + 4096;   // 1024-bin L2 hist
        for (int i = tid; i < 1024; i += 1024) s_h2[i] = 0;
        if (tid == 0) s_sc[2] = 0;
        __syncthreads();
        for (unsigned j = tid; j < m; j += 1024) {
            unsigned long long cv = cand[j];
            unsigned rel = (unsigned)(cv >> 32) - base19;
            if ((rel >> 10) == B1) {
                unsigned p = atomicAdd(&s_sc[2], 1u);
                if (p < 4096u) {
                    s_stash[p] = ((rel & 1023u) << 19) | (unsigned)cv;
                    atomicAdd(&s_h2[rel & 1023u], 1u);
                }
            }
        }
        __syncthreads();
        unsigned e = min(s_sc[2], 4096u);   // == eq <= 4096
        // level-2: parallel suffix scan, one bin per thread
        {
            int b = 1023 - tid;
            unsigned val = (tid < 1024) ? s_h2[b] : 0;
            unsigned excl = excl_scan1024(val, s_w, tid);
            if (excl < r1 && r1 <= excl + val) { s_sc[3] = (unsigned)b; s_sc[4] = r1 - excl; }
        }
        __syncthreads();
        unsigned tl2 = s_sc[3], r2 = s_sc[4];
        if (tid == 0) g_tl[batch] = (long long)((B1 << 10) | tl2);  // rel > tl wins
        // ties at the exact threshold: LOWEST index first (matches top_k)
        for (unsigned j = tid; j < e; j += 1024) {
            unsigned v = s_stash[j];
            unsigned r10 = v >> 19, idx = v & 0x7FFFFu;
            if (r10 == tl2) {
                unsigned rank = 0;
                for (unsigned l = 0; l < e; l++) {
                    unsigned w2 = s_stash[l];
                    rank += ((w2 >> 19) == tl2 && (w2 & 0x7FFFFu) < idx) ? 1u : 0u;
                }
                if (rank < r2) ob[idx] = xb[idx];
            }
        }
        return;
    }

    // ---------------- exact fallback: full recompute for this batch --------
    if (tid == 0) g_tl[batch] = 0x7FFFFFFFFFFFFFFFLL;   // scatter writes nothing
    if (tid < NC) s_fac[tid] = boost_factor((int)k, duty[tid]);
    for (int i = tid; i < NBINS; i += 1024) s_big[i] = 0;
    __syncthreads();
    const float4* x4 = (const float4*)xb;
    for (int q = tid; q < NPB4; q += 1024) {
        float f = s_fac[q / HW4];
        float4 v = x4[q];
        atomicAdd(&s_big[okey(v.x * f) >> 19], 1u);
        atomicAdd(&s_big[okey(v.y * f) >> 19], 1u);
        atomicAdd(&s_big[okey(v.z * f) >> 19], 1u);
        atomicAdd(&s_big[okey(v.w * f) >> 19], 1u);
    }
    __syncthreads();
    {   // parallel scan for exact bstar
        unsigned h[8], sum = 0;
        int top = NBINS - 1 - tid * 8;
        #pragma unroll
        for (int i = 0; i < 8; i++) { h[i] = s_big[top - i]; sum += h[i]; }
        unsigned excl = excl_scan1024(sum, s_w, tid);
        if (excl < k && k <= excl + sum) {
            unsigned c = excl;
            #pragma unroll
            for (int i = 0; i < 8; i++) {
                if (c + h[i] >= k) { s_sc[0] = (unsigned)(top - i); s_sc[1] = c; break; }
                c += h[i];
            }
        }
    }
    __syncthreads();
    unsigned bstar = s_sc[0];
    unsigned rr = k - s_sc[1];
    if (tid == 0) s_sc[2] = 0;
    __syncthreads();
    float4* o4 = (float4*)ob;
    for (int q = tid; q < NPB4; q += 1024) {
        float f = s_fac[q / HW4];
        float4 v = x4[q];
        unsigned k0 = okey(v.x * f), k1 = okey(v.y * f);
        unsigned k2 = okey(v.z * f), k3 = okey(v.w * f);
        unsigned b0 = k0 >> 19, b1 = k1 >> 19, b2 = k2 >> 19, b3 = k3 >> 19;
        float4 o;
        o.x = (b0 > bstar) ? v.x : 0.0f;
        o.y = (b1 > bstar) ? v.y : 0.0f;
        o.z = (b2 > bstar) ? v.z : 0.0f;
        o.w = (b3 > bstar) ? v.w : 0.0f;
        o4[q] = o;
        unsigned e = (unsigned)q * 4u;
        if (b0 == bstar) { unsigned p = atomicAdd(&s_sc[2], 1u);
            if (p < CAP) cand[p] = ((unsigned long long)k0 << 32) | (e + 0u); }
        if (b1 == bstar) { unsigned p = atomicAdd(&s_sc[2], 1u);
            if (p < CAP) cand[p] = ((unsigned long long)k1 << 32) | (e + 1u); }
        if (b2 == bstar) { unsigned p = atomicAdd(&s_sc[2], 1u);
            if (p < CAP) cand[p] = ((unsigned long long)k2 << 32) | (e + 2u); }
        if (b3 == bstar) { unsigned p = atomicAdd(&s_sc[2], 1u);
            if (p < CAP) cand[p] = ((unsigned long long)k3 << 32) | (e + 3u); }
    }
    __syncthreads();
    unsigned m2 = min(s_sc[2], (unsigned)CAP);
    if (rr >= m2) {
        for (unsigned j = tid; j < m2; j += 1024) {
            unsigned idx = (unsigned)cand[j];
            ob[idx] = xb[idx];
        }
        return;
    }
    unsigned fb19 = bstar << 19;
    // L1: 512 bins on rel>>10
    for (int i = tid; i < 512; i += 1024) s_big[i] = 0;
    __syncthreads();
    for (unsigned j = tid; j < m2; j += 1024) {
        unsigned rel = (unsigned)(cand[j] >> 32) - fb19;
        atomicAdd(&s_big[rel >> 10], 1u);
    }
    __syncthreads();
    if (tid == 0) {
        unsigned cum = 0;
        for (int b = 511;; b--) {
            unsigned h = s_big[b];
            if (cum + h >= rr) { s_sc[3] = (unsigned)b; s_sc[4] = cum; break; }
            cum += h;
        }
    }
    __syncthreads();
    unsigned tl1 = s_sc[3];
    unsigned r1 = rr - s_sc[4];
    unsigned* s_l2 = s_big + 1024;
    for (int i = tid; i < 1024; i += 1024) s_l2[i] = 0;
    __syncthreads();
    for (unsigned j = tid; j < m2; j += 1024) {
        unsigned rel = (unsigned)(cand[j] >> 32) - fb19;
        if ((rel >> 10) == tl1) atomicAdd(&s_l2[rel & 1023u], 1u);
    }
    __syncthreads();
    if (tid == 0) {
        unsigned cum = 0;
        for (int b = 1023;; b--) {
            unsigned h = s_l2[b];
            if (cum + h >= r1) { s_sc[5] = (unsigned)b; s_sc[6] = r1 - cum; break; }
            cum += h;
        }
    }
    __syncthreads();
    unsigned tl = (tl1 << 10) | s_sc[5];
    unsigned r2 = s_sc[6];
    for (unsigned j = tid; j < m2; j += 1024) {
        unsigned long long cv = cand[j];
        unsigned rel = (unsigned)(cv >> 32) - fb19;
        unsigned idx = (unsigned)cv;
        if (rel > tl) ob[idx] = xb[idx];
        else if (rel == tl) {
            unsigned rank = 0;
            for (unsigned l = 0; l < m2; l++) {
                unsigned long long cw = cand[l];
                rank += (((unsigned)(cw >> 32) - fb19) == tl &&
                         (unsigned)cw < idx) ? 1u : 0u;
            }
            if (rank < r2) ob[idx] = xb[idx];
        }
    }
}

// -------- kernel 4b: scatter winners above threshold, 8 CTAs/batch --------
__global__ void __launch_bounds__(256) scatter_kernel(float* __restrict__ out) {
    int batch = blockIdx.x / SCC;
    int slice = blockIdx.x % SCC;
    long long tl = g_tl[batch];
    if (tl == 0x7FFFFFFFFFFFFFFFLL) return;        // fallback already wrote all
    unsigned m = min(g_cand_cnt[batch], (unsigned)CAP);
    unsigned base19 = g_blo[batch] << 19;
    const unsigned long long* cand = &g_cand[(size_t)batch * CAP];
    const float*              cval = &g_cand_val[(size_t)batch * CAP];
    float* ob = out + (size_t)batch * NPB;
    unsigned per = (m + SCC - 1) / SCC;
    unsigned lo = slice * per;
    unsigned hi = min(lo + per, m);
    for (unsigned j = lo + threadIdx.x; j < hi; j += 256) {
        unsigned long long cv = cand[j];
        unsigned rel = (unsigned)(cv >> 32) - base19;
        if ((long long)rel > tl) ob[(unsigned)cv] = cval[j];
    }
}

extern "C" void kernel_launch(void* const* d_in, const int* in_sizes, int n_in,
                              void* d_out, int out_size) {
    const float* x    = (const float*)d_in[0];
    const float* duty = (const float*)d_in[1];
    const int*   kp   = (const int*)d_in[2];
    float*       out  = (float*)d_out;

    zero_kernel<<<256, 256>>>();
    sample_kernel<<<NB * CPB_S, 256>>>(x, duty, kp);
    window_kernel<<<NB, 1024>>>(kp);
    write_kernel<<<NB * CPB_C, 256>>>(x, duty, kp, out);
    select_kernel<<<NB, 1024>>>(x, duty, kp, out);
    scatter_kernel<<<NB * SCC, 256>>>(out);
}

// round 17
// speedup vs baseline: 1.4430x; 1.0004x over previous
#include <cuda_runtime.h>
#include <math.h>

// Problem constants (KWinners2d: B=64, C=128, H=W=56)
#define NB      64
#define NC      128
#define HW      3136
#define NPB     401408          // per-batch n = C*H*W
#define NPB4    (NPB/4)         // 100352 float4 per batch
#define HW4     784
#define NBINS   8192            // 13-bit coarse histogram
#define CAP     (1<<17)         // candidate buffer per batch
#define CPB_S   8               // CTAs per batch, sample pass
#define CPB_C   32              // CTAs per batch, write pass
#define SCC     8               // CTAs per batch, scatter pass
#define STAGE   1024            // per-CTA candidate staging entries
#define MS      50176           // sampled values per batch = NPB/8
#define MARGIN  350             // ~5.2 sigma of sampled-rank noise

// -------- global scratch (static __device__, no allocation) --------
// invariant: g_hist / g_cand_cnt / g_above are ZERO at kernel_launch entry.
// (zero-initialized at load; scatter_kernel re-zeroes g_hist, select_kernel
// re-zeroes the counters — so every call leaves the invariant restored.)
__device__ unsigned int       g_hist [NB * NBINS];   // sampled coarse hist
__device__ unsigned int       g_cand_cnt[NB];
__device__ unsigned int       g_m[NB];               // candidate count for scatter
__device__ unsigned int       g_bhi[NB];
__device__ unsigned int       g_blo[NB];
__device__ float              g_Thi[NB];             // float thresholds
__device__ float              g_Tlo[NB];
__device__ unsigned int       g_above[NB];
__device__ long long          g_tl[NB];              // rel threshold for scatter
__device__ unsigned long long g_cand[(size_t)NB * CAP];      // (key<<32)|idx
__device__ float              g_cand_val[(size_t)NB * CAP];  // original x value

// order-preserving key for f32: larger float -> larger uint
__device__ __forceinline__ unsigned okey(float f) {
    unsigned u = __float_as_uint(f);
    unsigned s = (unsigned)((int)u >> 31);
    return u ^ (s | 0x80000000u);
}
// inverse: float whose okey equals k
__device__ __forceinline__ float inv_okey(unsigned k) {
    unsigned u = (k & 0x80000000u) ? (k & 0x7FFFFFFFu) : ~k;
    return __uint_as_float(u);
}

__device__ __forceinline__ float boost_factor(int k, float duty) {
    float td = (float)((double)k / (double)NPB);
    float arg = td - duty;
    return (float)exp((double)arg);   // correctly-rounded f32 result
}

// block-wide exclusive prefix sum, blockDim.x == 1024 exactly
__device__ __forceinline__ unsigned excl_scan1024(unsigned v, unsigned* s_w, int tid) {
    __syncthreads();                              // protect s_w reuse
    int lane = tid & 31, wid = tid >> 5;
    unsigned inc = v;
    #pragma unroll
    for (int o = 1; o < 32; o <<= 1) {
        unsigned n = __shfl_up_sync(0xffffffffu, inc, o);
        if (lane >= o) inc += n;
    }
    if (lane == 31) s_w[wid] = inc;
    __syncthreads();
    if (wid == 0) {
        unsigned w = s_w[lane];
        #pragma unroll
        for (int o = 1; o < 32; o <<= 1) {
            unsigned n = __shfl_up_sync(0xffffffffu, w, o);
            if (lane >= o) w += n;
        }
        s_w[lane] = w;
    }
    __syncthreads();
    unsigned base = wid ? s_w[wid - 1] : 0u;
    return base + inc - v;
}

// -------- kernel 1: sampled coarse histogram, 8 CTAs/batch --------
__global__ void __launch_bounds__(256) sample_kernel(
        const float* __restrict__ x,
        const float* __restrict__ duty,
        const int* __restrict__ kp) {
    __shared__ unsigned s_hist[NBINS];
    __shared__ float    s_fac[NC];
    int tid = threadIdx.x;
    for (int i = tid; i < NBINS; i += 256) s_hist[i] = 0;
    if (tid < NC) s_fac[tid] = boost_factor(*kp, duty[tid]);
    __syncthreads();

    int batch = blockIdx.x / CPB_S;
    int slice = blockIdx.x % CPB_S;
    const float4* x4 = (const float4*)x + (size_t)batch * NPB4;
    int base = slice * (NPB4 / CPB_S);         // 12544 region per CTA
    // 1568 sampled float4: warp reads 32 contiguous float4 (512B), skips 8x
    for (int j = tid; j < 1568; j += 256) {
        int q = base + ((j >> 5) << 8) + (j & 31);
        float f = s_fac[q / HW4];
        float4 v = x4[q];
        unsigned b0 = okey(v.x * f) >> 19;
        unsigned b1 = okey(v.y * f) >> 19;
        unsigned b2 = okey(v.z * f) >> 19;
        unsigned b3 = okey(v.w * f) >> 19;
        unsigned c0 = 1, c1 = 1, c2 = 1, c3 = 1;
        if (b1 == b0) { c0++; c1 = 0; }
        if (b2 == b0) { c0++; c2 = 0; }
        else if (c1 && b2 == b1) { c1++; c2 = 0; }
        if (b3 == b0) { c0++; c3 = 0; }
        else if (c1 && b3 == b1) { c1++; c3 = 0; }
        else if (c2 && b3 == b2) { c2++; c3 = 0; }
        atomicAdd(&s_hist[b0], c0);
        if (c1) atomicAdd(&s_hist[b1], c1);
        if (c2) atomicAdd(&s_hist[b2], c2);
        if (c3) atomicAdd(&s_hist[b3], c3);
    }
    __syncthreads();
    unsigned* gh = &g_hist[batch * NBINS];
    for (int i = tid; i < NBINS; i += 256)
        if (s_hist[i]) atomicAdd(&gh[i], s_hist[i]);
}

// -------- kernel 2: pick window [b_lo, b_hi] + float thresholds ------------
__global__ void __launch_bounds__(1024) window_kernel(const int* __restrict__ kp) {
    __shared__ unsigned s_w[32];
    __shared__ unsigned s_res[2];
    int batch = blockIdx.x, tid = threadIdx.x;
    const unsigned* gh = &g_hist[batch * NBINS];
    unsigned h[8], sum = 0;
    int top = NBINS - 1 - tid * 8;
    #pragma unroll
    for (int i = 0; i < 8; i++) { h[i] = gh[top - i]; sum += h[i]; }
    unsigned excl = excl_scan1024(sum, s_w, tid);   // counts in bins above chunk

    unsigned k  = (unsigned)(*kp);
    unsigned ks = (unsigned)((unsigned long long)k * MS / NPB);
    unsigned khi = (ks > MARGIN) ? ks - MARGIN : 1u;
    unsigned klo = ks + MARGIN; if (klo > MS) klo = MS;

    if (excl < khi && khi <= excl + sum) {
        unsigned c = excl;
        #pragma unroll
        for (int i = 0; i < 8; i++) { if (c + h[i] >= khi) { s_res[0] = (unsigned)(top - i); break; } c += h[i]; }
    }
    if (excl < klo && klo <= excl + sum) {
        unsigned c = excl;
        #pragma unroll
        for (int i = 0; i < 8; i++) { if (c + h[i] >= klo) { s_res[1] = (unsigned)(top - i); break; } c += h[i]; }
    }
    __syncthreads();
    if (tid == 0) {
        unsigned bhi = s_res[0], blo = s_res[1];
        if (bhi > 8190u) bhi = 8190u;          // keep (bhi+1)<<19 in 32 bits
        if (blo > bhi) blo = bhi;
        if (bhi == 4095u) bhi = 4096u;         // avoid T_hi == +/-0.0
        if (blo == 4096u) blo = 4095u;         // avoid T_lo == +/-0.0
        g_bhi[batch] = bhi;
        g_blo[batch] = blo;
        g_Thi[batch] = inv_okey((bhi + 1u) << 19);
        g_Tlo[batch] = inv_okey(blo << 19);
    }
}

// -------- kernel 3: write output, exact above-count, stage window cands ----
__global__ void __launch_bounds__(256, 8) write_kernel(
        const float* __restrict__ x,
        const float* __restrict__ duty,
        const int* __restrict__ kp,
        float* __restrict__ out) {
    __shared__ float              s_fac[4];
    __shared__ unsigned long long s_buf[STAGE];
    __shared__ float              s_val[STAGE];
    __shared__ unsigned           s_cnt, s_w, s_base;
    int tid = threadIdx.x;
    int batch = blockIdx.x / CPB_C;
    int slice = blockIdx.x % CPB_C;
    if (tid < NC / CPB_C)                       // only this CTA's 4 channels
        s_fac[tid] = boost_factor(*kp, duty[slice * (NC / CPB_C) + tid]);
    if (tid == 0) { s_cnt = 0; s_w = 0; }
    __syncthreads();

    float Thi = g_Thi[batch];
    float Tlo = g_Tlo[batch];
    const float4* x4 = (const float4*)x + (size_t)batch * NPB4;
    float4*       o4 = (float4*)out     + (size_t)batch * NPB4;
    const int PER = NPB4 / CPB_C;              // 3136 = 4 channels
    int qb = slice * PER;
    unsigned wc = 0;

    #pragma unroll 2
    for (int i = tid; i < PER; i += 256) {
        int q = qb + i;
        float f = s_fac[i / HW4];              // channel within CTA: 0..3
        float4 v = x4[q];
        float vf0 = v.x * f, vf1 = v.y * f, vf2 = v.z * f, vf3 = v.w * f;
        bool w0 = vf0 >= Thi, w1 = vf1 >= Thi, w2 = vf2 >= Thi, w3 = vf3 >= Thi;
        float4 o;
        o.x = w0 ? v.x : 0.0f;
        o.y = w1 ? v.y : 0.0f;
        o.z = w2 ? v.z : 0.0f;
        o.w = w3 ? v.w : 0.0f;
        o4[q] = o;
        wc += (unsigned)w0 + (unsigned)w1 + (unsigned)w2 + (unsigned)w3;
        bool c0 = (vf0 >= Tlo) & !w0;
        bool c1 = (vf1 >= Tlo) & !w1;
        bool c2 = (vf2 >= Tlo) & !w2;
        bool c3 = (vf3 >= Tlo) & !w3;
        if (c0 | c1 | c2 | c3) {                // ~1.5% of iterations
            unsigned e = (unsigned)q * 4u;
            if (c0) {
                unsigned p = atomicAdd(&s_cnt, 1u);
                unsigned long long cv = ((unsigned long long)okey(vf0) << 32) | (e + 0u);
                if (p < STAGE) { s_buf[p] = cv; s_val[p] = v.x; }
                else { unsigned g = atomicAdd(&g_cand_cnt[batch], 1u);
                       if (g < CAP) { g_cand[(size_t)batch * CAP + g] = cv;
                                      g_cand_val[(size_t)batch * CAP + g] = v.x; } }
            }
            if (c1) {
                unsigned p = atomicAdd(&s_cnt, 1u);
                unsigned long long cv = ((unsigned long long)okey(vf1) << 32) | (e + 1u);
                if (p < STAGE) { s_buf[p] = cv; s_val[p] = v.y; }
                else { unsigned g = atomicAdd(&g_cand_cnt[batch], 1u);
                       if (g < CAP) { g_cand[(size_t)batch * CAP + g] = cv;
                                      g_cand_val[(size_t)batch * CAP + g] = v.y; } }
            }
            if (c2) {
                unsigned p = atomicAdd(&s_cnt, 1u);
                unsigned long long cv = ((unsigned long long)okey(vf2) << 32) | (e + 2u);
                if (p < STAGE) { s_buf[p] = cv; s_val[p] = v.z; }
                else { unsigned g = atomicAdd(&g_cand_cnt[batch], 1u);
                       if (g < CAP) { g_cand[(size_t)batch * CAP + g] = cv;
                                      g_cand_val[(size_t)batch * CAP + g] = v.z; } }
            }
            if (c3) {
                unsigned p = atomicAdd(&s_cnt, 1u);
                unsigned long long cv = ((unsigned long long)okey(vf3) << 32) | (e + 3u);
                if (p < STAGE) { s_buf[p] = cv; s_val[p] = v.w; }
                else { unsigned g = atomicAdd(&g_cand_cnt[batch], 1u);
                       if (g < CAP) { g_cand[(size_t)batch * CAP + g] = cv;
                                      g_cand_val[(size_t)batch * CAP + g] = v.w; } }
            }
        }
    }
    // exact winners-above-window count: one global atomic per CTA
    #pragma unroll
    for (int o = 16; o; o >>= 1) wc += __shfl_down_sync(0xffffffffu, wc, o);
    if ((tid & 31) == 0 && wc) atomicAdd(&s_w, wc);
    __syncthreads();
    if (tid == 0) {
        if (s_w) atomicAdd(&g_above[batch], s_w);
        s_base = atomicAdd(&g_cand_cnt[batch], min(s_cnt, (unsigned)STAGE));
    }
    __syncthreads();
    unsigned cnt = min(s_cnt, (unsigned)STAGE);
    unsigned cb = s_base;
    for (unsigned j = tid; j < cnt; j += 256) {
        unsigned pos = cb + j;
        if (pos < CAP) {
            g_cand[(size_t)batch * CAP + pos] = s_buf[j];
            g_cand_val[(size_t)batch * CAP + pos] = s_val[j];
        }
    }
}

// -------- kernel 4a: exact threshold + tie resolution (or full fallback) ---
// on every exit path: publishes g_tl/g_m and re-zeroes g_cand_cnt/g_above
__global__ void __launch_bounds__(1024) select_kernel(
        const float* __restrict__ x,
        const float* __restrict__ duty,
        const int* __restrict__ kp,
        float* __restrict__ out) {
    __shared__ unsigned s_w[32];
    __shared__ float    s_fac[NC];
    __shared__ unsigned s_big[NBINS];     // hist, then stash[0..4095] + L2 hist[4096..5119]
    __shared__ unsigned s_sc[8];
    int batch = blockIdx.x, tid = threadIdx.x;
    unsigned k = (unsigned)(*kp);
    unsigned m = g_cand_cnt[batch];
    unsigned above = g_above[batch];
    unsigned blo = g_blo[batch], bhi = g_bhi[batch];
    unsigned long long* cand = &g_cand[(size_t)batch * CAP];
    const float* xb = x   + (size_t)batch * NPB;
    float*       ob = out + (size_t)batch * NPB;

    bool valid = (above < k) && (k <= above + m) && (m <= (unsigned)CAP) &&
                 (bhi - blo < 16u);
    unsigned r = 0, B1 = 0, g1 = 0, eq = 0;
    unsigned base19 = blo << 19;

    if (valid) {
        r = k - above;
        if (r >= m) {                       // everything in the window wins
            if (tid == 0) {
                g_tl[batch] = -1LL;         // scatter writes all
                g_m[batch] = m;
                g_cand_cnt[batch] = 0;      // restore zero-invariant
                g_above[batch] = 0;
            }
            return;
        }
        // build rel-key level-1 histogram (rel>>10, 8192 bins) over candidates
        for (int i = tid; i < NBINS; i += 1024) s_big[i] = 0;
        __syncthreads();
        for (unsigned j = tid; j < m; j += 1024) {
            unsigned rel = (unsigned)(cand[j] >> 32) - base19;   // < 2^23
            atomicAdd(&s_big[rel >> 10], 1u);
        }
        __syncthreads();
        // parallel suffix scan for rank r
        unsigned h[8], sum = 0;
        int top = NBINS - 1 - tid * 8;
        #pragma unroll
        for (int i = 0; i < 8; i++) { h[i] = s_big[top - i]; sum += h[i]; }
        unsigned excl = excl_scan1024(sum, s_w, tid);
        if (excl < r && r <= excl + sum) {
            unsigned c = excl;
            #pragma unroll
            for (int i = 0; i < 8; i++) {
                if (c + h[i] >= r) { s_sc[0] = (unsigned)(top - i); s_sc[1] = c; break; }
                c += h[i];
            }
        }
        __syncthreads();
        B1 = s_sc[0]; g1 = s_sc[1];
        eq = s_big[B1];
        if (eq > 4096u) valid = false;      // stash overflow -> fallback
        __syncthreads();
    }

    if (valid) {
        // ---------------- fast exact path: threshold + ties only ----------
        unsigned r1 = r - g1;               // needed among the B1 group
        unsigned* s_stash = s_big;          // 4096 packed (rel10<<19)|idx
        unsigned* s_h2    = s_big + 4096;   // 1024-bin L2 hist
        for (int i = tid; i < 1024; i += 1024) s_h2[i] = 0;
        if (tid == 0) s_sc[2] = 0;
        __syncthreads();
        for (unsigned j = tid; j < m; j += 1024) {
            unsigned long long cv = cand[j];
            unsigned rel = (unsigned)(cv >> 32) - base19;
            if ((rel >> 10) == B1) {
                unsigned p = atomicAdd(&s_sc[2], 1u);
                if (p < 4096u) {
                    s_stash[p] = ((rel & 1023u) << 19) | (unsigned)cv;
                    atomicAdd(&s_h2[rel & 1023u], 1u);
                }
            }
        }
        __syncthreads();
        unsigned e = min(s_sc[2], 4096u);   // == eq <= 4096
        // level-2: parallel suffix scan, one bin per thread
        {
            int b = 1023 - tid;
            unsigned val = (tid < 1024) ? s_h2[b] : 0;
            unsigned excl = excl_scan1024(val, s_w, tid);
            if (excl < r1 && r1 <= excl + val) { s_sc[3] = (unsigned)b; s_sc[4] = r1 - excl; }
        }
        __syncthreads();
        unsigned tl2 = s_sc[3], r2 = s_sc[4];
        if (tid == 0) {
            g_tl[batch] = (long long)((B1 << 10) | tl2);  // rel > tl wins
            g_m[batch] = m;
            g_cand_cnt[batch] = 0;          // restore zero-invariant
            g_above[batch] = 0;
        }
        // ties at the exact threshold: LOWEST index first (matches top_k)
        for (unsigned j = tid; j < e; j += 1024) {
            unsigned v = s_stash[j];
            unsigned r10 = v >> 19, idx = v & 0x7FFFFu;
            if (r10 == tl2) {
                unsigned rank = 0;
                for (unsigned l = 0; l < e; l++) {
                    unsigned w2 = s_stash[l];
                    rank += ((w2 >> 19) == tl2 && (w2 & 0x7FFFFu) < idx) ? 1u : 0u;
                }
                if (rank < r2) ob[idx] = xb[idx];
            }
        }
        return;
    }

    // ---------------- exact fallback: full recompute for this batch --------
    if (tid == 0) {
        g_tl[batch] = 0x7FFFFFFFFFFFFFFFLL;  // scatter writes nothing
        g_m[batch] = 0;
        g_cand_cnt[batch] = 0;               // restore zero-invariant
        g_above[batch] = 0;
    }
    if (tid < NC) s_fac[tid] = boost_factor((int)k, duty[tid]);
    for (int i = tid; i < NBINS; i += 1024) s_big[i] = 0;
    __syncthreads();
    const float4* x4 = (const float4*)xb;
    for (int q = tid; q < NPB4; q += 1024) {
        float f = s_fac[q / HW4];
        float4 v = x4[q];
        atomicAdd(&s_big[okey(v.x * f) >> 19], 1u);
        atomicAdd(&s_big[okey(v.y * f) >> 19], 1u);
        atomicAdd(&s_big[okey(v.z * f) >> 19], 1u);
        atomicAdd(&s_big[okey(v.w * f) >> 19], 1u);
    }
    __syncthreads();
    {   // parallel scan for exact bstar
        unsigned h[8], sum = 0;
        int top = NBINS - 1 - tid * 8;
        #pragma unroll
        for (int i = 0; i < 8; i++) { h[i] = s_big[top - i]; sum += h[i]; }
        unsigned excl = excl_scan1024(sum, s_w, tid);
        if (excl < k && k <= excl + sum) {
            unsigned c = excl;
            #pragma unroll
            for (int i = 0; i < 8; i++) {
                if (c + h[i] >= k) { s_sc[0] = (unsigned)(top - i); s_sc[1] = c; break; }
                c += h[i];
            }
        }
    }
    __syncthreads();
    unsigned bstar = s_sc[0];
    unsigned rr = k - s_sc[1];
    if (tid == 0) s_sc[2] = 0;
    __syncthreads();
    float4* o4 = (float4*)ob;
    for (int q = tid; q < NPB4; q += 1024) {
        float f = s_fac[q / HW4];
        float4 v = x4[q];
        unsigned k0 = okey(v.x * f), k1 = okey(v.y * f);
        unsigned k2 = okey(v.z * f), k3 = okey(v.w * f);
        unsigned b0 = k0 >> 19, b1 = k1 >> 19, b2 = k2 >> 19, b3 = k3 >> 19;
        float4 o;
        o.x = (b0 > bstar) ? v.x : 0.0f;
        o.y = (b1 > bstar) ? v.y : 0.0f;
        o.z = (b2 > bstar) ? v.z : 0.0f;
        o.w = (b3 > bstar) ? v.w : 0.0f;
        o4[q] = o;
        unsigned e = (unsigned)q * 4u;
        if (b0 == bstar) { unsigned p = atomicAdd(&s_sc[2], 1u);
            if (p < CAP) cand[p] = ((unsigned long long)k0 << 32) | (e + 0u); }
        if (b1 == bstar) { unsigned p = atomicAdd(&s_sc[2], 1u);
            if (p < CAP) cand[p] = ((unsigned long long)k1 << 32) | (e + 1u); }
        if (b2 == bstar) { unsigned p = atomicAdd(&s_sc[2], 1u);
            if (p < CAP) cand[p] = ((unsigned long long)k2 << 32) | (e + 2u); }
        if (b3 == bstar) { unsigned p = atomicAdd(&s_sc[2], 1u);
            if (p < CAP) cand[p] = ((unsigned long long)k3 << 32) | (e + 3u); }
    }
    __syncthreads();
    unsigned m2 = min(s_sc[2], (unsigned)CAP);
    if (rr >= m2) {
        for (unsigned j = tid; j < m2; j += 1024) {
            unsigned idx = (unsigned)cand[j];
            ob[idx] = xb[idx];
        }
        return;
    }
    unsigned fb19 = bstar << 19;
    // L1: 512 bins on rel>>10
    for (int i = tid; i < 512; i += 1024) s_big[i] = 0;
    __syncthreads();
    for (unsigned j = tid; j < m2; j += 1024) {
        unsigned rel = (unsigned)(cand[j] >> 32) - fb19;
        atomicAdd(&s_big[rel >> 10], 1u);
    }
    __syncthreads();
    if (tid == 0) {
        unsigned cum = 0;
        for (int b = 511;; b--) {
            unsigned h = s_big[b];
            if (cum + h >= rr) { s_sc[3] = (unsigned)b; s_sc[4] = cum; break; }
            cum += h;
        }
    }
    __syncthreads();
    unsigned tl1 = s_sc[3];
    unsigned r1 = rr - s_sc[4];
    unsigned* s_l2 = s_big + 1024;
    for (int i = tid; i < 1024; i += 1024) s_l2[i] = 0;
    __syncthreads();
    for (unsigned j = tid; j < m2; j += 1024) {
        unsigned rel = (unsigned)(cand[j] >> 32) - fb19;
        if ((rel >> 10) == tl1) atomicAdd(&s_l2[rel & 1023u], 1u);
    }
    __syncthreads();
    if (tid == 0) {
        unsigned cum = 0;
        for (int b = 1023;; b--) {
            unsigned h = s_l2[b];
            if (cum + h >= r1) { s_sc[5] = (unsigned)b; s_sc[6] = r1 - cum; break; }
            cum += h;
        }
    }
    __syncthreads();
    unsigned tl = (tl1 << 10) | s_sc[5];
    unsigned r2 = s_sc[6];
    for (unsigned j = tid; j < m2; j += 1024) {
        unsigned long long cv = cand[j];
        unsigned rel = (unsigned)(cv >> 32) - fb19;
        unsigned idx = (unsigned)cv;
        if (rel > tl) ob[idx] = xb[idx];
        else if (rel == tl) {
            unsigned rank = 0;
            for (unsigned l = 0; l < m2; l++) {
                unsigned long long cw = cand[l];
                rank += (((unsigned)(cw >> 32) - fb19) == tl &&
                         (unsigned)cw < idx) ? 1u : 0u;
            }
            if (rank < r2) ob[idx] = xb[idx];
        }
    }
}

// -------- kernel 4b: scatter winners above threshold, 8 CTAs/batch --------
// also re-zeroes g_hist for the next graph replay (dead after window_kernel)
__global__ void __launch_bounds__(256) scatter_kernel(float* __restrict__ out) {
    int tid = threadIdx.x;
    // zero this CTA's 1024-entry slice of g_hist (coalesced, overlapped)
    {
        int base = blockIdx.x * (NB * NBINS / (NB * SCC));   // 1024 per CTA
        #pragma unroll
        for (int i = 0; i < 4; i++) g_hist[base + tid + i * 256] = 0;
    }
    int batch = blockIdx.x / SCC;
    int slice = blockIdx.x % SCC;
    long long tl = g_tl[batch];
    if (tl == 0x7FFFFFFFFFFFFFFFLL) return;        // fallback already wrote all
    unsigned m = min(g_m[batch], (unsigned)CAP);
    unsigned base19 = g_blo[batch] << 19;
    const unsigned long long* cand = &g_cand[(size_t)batch * CAP];
    const float*              cval = &g_cand_val[(size_t)batch * CAP];
    float* ob = out + (size_t)batch * NPB;
    unsigned per = (m + SCC - 1) / SCC;
    unsigned lo = slice * per;
    unsigned hi = min(lo + per, m);
    for (unsigned j = lo + tid; j < hi; j += 256) {
        unsigned long long cv = cand[j];
        unsigned rel = (unsigned)(cv >> 32) - base19;
        if ((long long)rel > tl) ob[(unsigned)cv] = cval[j];
    }
}

extern "C" void kernel_launch(void* const* d_in, const int* in_sizes, int n_in,
                              void* d_out, int out_size) {
    const float* x    = (const float*)d_in[0];
    const float* duty = (const float*)d_in[1];
    const int*   kp   = (const int*)d_in[2];
    float*       out  = (float*)d_out;

    sample_kernel<<<NB * CPB_S, 256>>>(x, duty, kp);
    window_kernel<<<NB, 1024>>>(kp);
    write_kernel<<<NB * CPB_C, 256>>>(x, duty, kp, out);
    select_kernel<<<NB, 1024>>>(x, duty, kp, out);
    scatter_kernel<<<NB * SCC, 256>>>(out);
}